// round 5
// baseline (speedup 1.0000x reference)
#include <cuda_runtime.h>

// out[i,j,k] = C[i,j,k] * x[i,j]
// B=4096, INPUT_SIZE=512, EMBED_DIM=64 -> n = 2^27 floats, n4 = 2^25 float4
//
// v5: 256 threads x 16 unroll, block-contiguous 4096-float4 (64KB) tiles.
// Exact-division fast kernel (no predication); generic fallback for safety.
// Streaming hints: __ldcs on C, __stcs on out; x stays L1/L2-resident.

#define THREADS 256
#define UNROLL  16

__global__ __launch_bounds__(THREADS)
void bcast_mul_exact(const float* __restrict__ x,
                     const float4* __restrict__ C4,
                     float4* __restrict__ out4) {
    const unsigned base = blockIdx.x * (THREADS * UNROLL) + threadIdx.x;

    float4 c[UNROLL];
    float  s[UNROLL];
#pragma unroll
    for (int j = 0; j < UNROLL; j++) {
        unsigned i = base + j * THREADS;
        c[j] = __ldcs(&C4[i]);
        s[j] = __ldg(&x[i >> 4]);          // 16 float4-groups per x scalar
    }
#pragma unroll
    for (int j = 0; j < UNROLL; j++) {
        unsigned i = base + j * THREADS;
        float4 o;
        o.x = c[j].x * s[j];
        o.y = c[j].y * s[j];
        o.z = c[j].z * s[j];
        o.w = c[j].w * s[j];
        __stcs(&out4[i], o);
    }
}

__global__ void bcast_mul_generic(const float* __restrict__ x,
                                  const float4* __restrict__ C4,
                                  float4* __restrict__ out4,
                                  unsigned n4) {
    unsigned i = blockIdx.x * blockDim.x + threadIdx.x;
    if (i < n4) {
        float s = __ldg(&x[i >> 4]);
        float4 c = __ldcs(&C4[i]);
        float4 o;
        o.x = c.x * s; o.y = c.y * s; o.z = c.z * s; o.w = c.w * s;
        __stcs(&out4[i], o);
    }
}

extern "C" void kernel_launch(void* const* d_in, const int* in_sizes, int n_in,
                              void* d_out, int out_size) {
    const float* x;
    const float* C;
    if (in_sizes[0] < in_sizes[1]) {
        x = (const float*)d_in[0];
        C = (const float*)d_in[1];
    } else {
        x = (const float*)d_in[1];
        C = (const float*)d_in[0];
    }

    unsigned n4 = (unsigned)((long long)out_size >> 2);   // 33,554,432
    const unsigned per_block = THREADS * UNROLL;          // 4096

    if (n4 % per_block == 0) {
        bcast_mul_exact<<<n4 / per_block, THREADS>>>(
            x, (const float4*)C, (float4*)d_out);
    } else {
        bcast_mul_generic<<<(n4 + 255) / 256, 256>>>(
            x, (const float4*)C, (float4*)d_out, n4);
    }
}

// round 6
// speedup vs baseline: 1.0071x; 1.0071x over previous
#include <cuda_runtime.h>

// out[i,j,k] = C[i,j,k] * x[i,j]
// B=4096, INPUT_SIZE=512, EMBED_DIM=64 -> n = 2^27 floats, n4 = 2^25 float4
//
// FINAL (v4 config — best measured wall time, 157.8us, 85% of HBM spec):
//  - 512 threads x 8 unroll, block-contiguous 4096-float4 (64KB r + 64KB w) tiles
//  - exact-division fast kernel, zero predication; generic fallback for safety
//  - __ldcs on C (read-once), __stcs on out (write-once), __ldg on x (L2-resident)
// Kernel is DRAM-turnaround-bound: traffic is minimal (1.032 GB) and achieved
// BW is pinned at ~6.75 TB/s across all MLP/occupancy configs tested (R2-R5).

#define THREADS 512
#define UNROLL  8

__global__ __launch_bounds__(THREADS)
void bcast_mul_exact(const float* __restrict__ x,
                     const float4* __restrict__ C4,
                     float4* __restrict__ out4) {
    const unsigned base = blockIdx.x * (THREADS * UNROLL) + threadIdx.x;

    float4 c[UNROLL];
    float  s[UNROLL];
#pragma unroll
    for (int j = 0; j < UNROLL; j++) {
        unsigned i = base + j * THREADS;
        c[j] = __ldcs(&C4[i]);
        s[j] = __ldg(&x[i >> 4]);          // 16 float4-groups per x scalar
    }
#pragma unroll
    for (int j = 0; j < UNROLL; j++) {
        unsigned i = base + j * THREADS;
        float4 o;
        o.x = c[j].x * s[j];
        o.y = c[j].y * s[j];
        o.z = c[j].z * s[j];
        o.w = c[j].w * s[j];
        __stcs(&out4[i], o);
    }
}

__global__ void bcast_mul_generic(const float* __restrict__ x,
                                  const float4* __restrict__ C4,
                                  float4* __restrict__ out4,
                                  unsigned n4) {
    unsigned i = blockIdx.x * blockDim.x + threadIdx.x;
    if (i < n4) {
        float s = __ldg(&x[i >> 4]);
        float4 c = __ldcs(&C4[i]);
        float4 o;
        o.x = c.x * s; o.y = c.y * s; o.z = c.z * s; o.w = c.w * s;
        __stcs(&out4[i], o);
    }
}

extern "C" void kernel_launch(void* const* d_in, const int* in_sizes, int n_in,
                              void* d_out, int out_size) {
    const float* x;
    const float* C;
    if (in_sizes[0] < in_sizes[1]) {
        x = (const float*)d_in[0];
        C = (const float*)d_in[1];
    } else {
        x = (const float*)d_in[1];
        C = (const float*)d_in[0];
    }

    unsigned n4 = (unsigned)((long long)out_size >> 2);   // 33,554,432
    const unsigned per_block = THREADS * UNROLL;          // 4096

    if (n4 % per_block == 0) {
        bcast_mul_exact<<<n4 / per_block, THREADS>>>(
            x, (const float4*)C, (float4*)d_out);
    } else {
        bcast_mul_generic<<<(n4 + 255) / 256, 256>>>(
            x, (const float4*)C, (float4*)d_out, n4);
    }
}